// round 12
// baseline (speedup 1.0000x reference)
#include <cuda_runtime.h>

typedef unsigned long long ULL;

__device__ __forceinline__ ULL pack2(float a, float b){
    ULL r; asm("mov.b64 %0, {%1, %2};" : "=l"(r) : "f"(a), "f"(b)); return r;
}
__device__ __forceinline__ void unpack2(ULL v, float& a, float& b){
    asm("mov.b64 {%0, %1}, %2;" : "=f"(a), "=f"(b) : "l"(v));
}
// Packed dual-fp32 ops (Blackwell f32x2) — ptxas never auto-fuses; must be PTX.
__device__ __forceinline__ ULL ffma2(ULL a, ULL b, ULL c){
    ULL d; asm("fma.rn.f32x2 %0, %1, %2, %3;" : "=l"(d) : "l"(a), "l"(b), "l"(c)); return d;
}
__device__ __forceinline__ ULL fadd2(ULL a, ULL b){
    ULL d; asm("add.rn.f32x2 %0, %1, %2;" : "=l"(d) : "l"(a), "l"(b)); return d;
}
__device__ __forceinline__ ULL fmul2(ULL a, ULL b){
    ULL d; asm("mul.rn.f32x2 %0, %1, %2;" : "=l"(d) : "l"(a), "l"(b)); return d;
}
__device__ __forceinline__ float celu1(float v){
    return v > 0.f ? v : (__expf(v) - 1.f);
}

// ---- device scratch (static __device__ arrays: the allowed scratch path) ----
__device__ int   g_start[32769];
__device__ float g_P[32768 * 1024];     // 128 MB intermediate P = x^T M per point

// Boundary-detection segment starts: g_start[n] = first edge i with out_index[i] >= n.
__global__ void starts_kernel(const int* __restrict__ out_index, int E, int Npts){
    int i = blockIdx.x * blockDim.x + threadIdx.x;
    if (i >= E) return;
    const int cur  = out_index[i];
    const int prev = (i == 0) ? -1 : out_index[i - 1];
    for (int n = prev + 1; n <= cur; ++n) g_start[n] = i;
    if (i == E - 1)
        for (int n = cur + 1; n <= Npts; ++n) g_start[n] = E;
}

// ---------------- Phase 1: per-point edge aggregation -> P ----------------
// One warp per point, 2 edges/iter (half-warp 0 -> edge t, half 1 -> edge t+1).
// acc layout: channel-pairs in the f32x2 lanes: acc0[q] = (P[2q][l], P[2q+1][l]),
// acc1[q] = (P[2q][l+32], P[2q+1][l+32]). The x operand of the outer product
// arrives packed from warp-uniform LDG.128 of the x_in row (no shfl, no dup-MOV).
// 1/cnt normalization folded into the final P store.
__global__ __launch_bounds__(128)
void edge_kernel(const float* __restrict__ x_in, const float* __restrict__ pos_in,
                 const float* __restrict__ pos_out, const int* __restrict__ in_index,
                 const float* __restrict__ W1, const float* __restrict__ W2, int Npts)
{
    const int w = threadIdx.x >> 5;
    const int l = threadIdx.x & 31;
    const int n = blockIdx.x * 4 + w;
    if (n >= Npts) return;

    const int half = l >> 4;
    const int j16  = l & 15;

    const int s    = g_start[n];
    const int cnt  = g_start[n + 1] - s;
    const float inv = cnt > 0 ? 1.f / (float)cnt : 0.f;
    const int lim  = cnt < 64 ? cnt : 64;   // reference drops edges past K=64 slots

    const float w1c0 = W1[j16], w1c1 = W1[16 + j16], w1c2 = W1[32 + j16];

    // W2 col-pair packing for the M dot products: w2col[j] = (W2[j][l], W2[j][l+32])
    ULL w2col[16];
    #pragma unroll
    for (int j = 0; j < 16; ++j)
        w2col[j] = pack2(W2[j * 64 + l], W2[j * 64 + l + 32]);

    const float pox = pos_out[n * 3], poy = pos_out[n * 3 + 1], poz = pos_out[n * 3 + 2];

    ULL acc0[8], acc1[8];
    #pragma unroll
    for (int q = 0; q < 8; ++q) { acc0[q] = 0ull; acc1[q] = 0ull; }

    // pipeline slots: (idx, d0, d1, d2) for this half's edge of pairs t and t+2.
    int   aix = 0; float ad0 = 0.f, ad1 = 0.f, ad2 = 0.f;
    int   bix = 0; float bd0 = 0.f, bd1 = 0.f, bd2 = 0.f;
    if (half < lim) {
        aix = in_index[s + half];
        ad0 = pos_in[aix * 3]     - pox;
        ad1 = pos_in[aix * 3 + 1] - poy;
        ad2 = pos_in[aix * 3 + 2] - poz;
    }
    if (2 + half < lim) {
        bix = in_index[s + 2 + half];
        bd0 = pos_in[bix * 3]     - pox;
        bd1 = pos_in[bix * 3 + 1] - poy;
        bd2 = pos_in[bix * 3 + 2] - poz;
    }

    for (int t = 0; t < lim; t += 2) {
        // prefetch pair t+4
        int nix = 0; float nd0 = 0.f, nd1 = 0.f, nd2 = 0.f;
        {
            const int e = t + 4 + half;
            if (e < lim) {
                nix = in_index[s + e];
                nd0 = pos_in[nix * 3]     - pox;
                nd1 = pos_in[nix * 3 + 1] - poy;
                nd2 = pos_in[nix * 3 + 2] - poz;
            }
        }

        // edge indices of the current pair, uniform across the warp
        const int ia = __shfl_sync(0xffffffffu, aix, 0);
        const int ib = __shfl_sync(0xffffffffu, aix, 16);
        const float4* xrA = (const float4*)(x_in + (ULL)ia * 16);
        const float4* xrB = (const float4*)(x_in + (ULL)ib * 16);
        // first half of the x rows (uniform broadcast LDG.128; latency covered by m-loop)
        const float4 xa0 = xrA[0], xa1 = xrA[1];
        const float4 xb0 = xrB[0], xb1 = xrB[1];

        // h for my half's edge; inactive edge -> d=0 -> h=celu(0)=0 -> M=0 kills x junk
        const float h = celu1(fmaf(ad2, w1c2, fmaf(ad1, w1c1, ad0 * w1c0)));

        // M col-pairs for edge A (h in lanes 0-15) and edge B (lanes 16-31)
        ULL mA0 = 0ull, mA1 = 0ull, mB0 = 0ull, mB1 = 0ull;
        #pragma unroll
        for (int j = 0; j < 8; ++j) {
            const float a0 = __shfl_sync(0xffffffffu, h, j);
            const float b0 = __shfl_sync(0xffffffffu, h, 16 + j);
            const float a1 = __shfl_sync(0xffffffffu, h, 8 + j);
            const float b1 = __shfl_sync(0xffffffffu, h, 24 + j);
            mA0 = ffma2(pack2(a0, a0), w2col[j],     mA0);
            mB0 = ffma2(pack2(b0, b0), w2col[j],     mB0);
            mA1 = ffma2(pack2(a1, a1), w2col[8 + j], mA1);
            mB1 = ffma2(pack2(b1, b1), w2col[8 + j], mB1);
        }
        // second half of the x rows
        const float4 xa2 = xrA[2], xa3 = xrA[3];
        const float4 xb2 = xrB[2], xb3 = xrB[3];

        float mAl, mAr, mBl, mBr;
        { ULL m = fadd2(mA0, mA1); float a, b; unpack2(m, a, b); mAl = celu1(a); mAr = celu1(b); }
        { ULL m = fadd2(mB0, mB1); float a, b; unpack2(m, a, b); mBl = celu1(a); mBr = celu1(b); }
        const ULL mAld = pack2(mAl, mAl), mArd = pack2(mAr, mAr);
        const ULL mBld = pack2(mBl, mBl), mBrd = pack2(mBr, mBr);

        // outer-product accumulation: x channel-pairs packed straight from float4 regs
        {
            const ULL pA01 = pack2(xa0.x, xa0.y), pA23 = pack2(xa0.z, xa0.w);
            const ULL pA45 = pack2(xa1.x, xa1.y), pA67 = pack2(xa1.z, xa1.w);
            const ULL pB01 = pack2(xb0.x, xb0.y), pB23 = pack2(xb0.z, xb0.w);
            const ULL pB45 = pack2(xb1.x, xb1.y), pB67 = pack2(xb1.z, xb1.w);
            acc0[0] = ffma2(pA01, mAld, acc0[0]);  acc1[0] = ffma2(pA01, mArd, acc1[0]);
            acc0[1] = ffma2(pA23, mAld, acc0[1]);  acc1[1] = ffma2(pA23, mArd, acc1[1]);
            acc0[2] = ffma2(pA45, mAld, acc0[2]);  acc1[2] = ffma2(pA45, mArd, acc1[2]);
            acc0[3] = ffma2(pA67, mAld, acc0[3]);  acc1[3] = ffma2(pA67, mArd, acc1[3]);
            acc0[0] = ffma2(pB01, mBld, acc0[0]);  acc1[0] = ffma2(pB01, mBrd, acc1[0]);
            acc0[1] = ffma2(pB23, mBld, acc0[1]);  acc1[1] = ffma2(pB23, mBrd, acc1[1]);
            acc0[2] = ffma2(pB45, mBld, acc0[2]);  acc1[2] = ffma2(pB45, mBrd, acc1[2]);
            acc0[3] = ffma2(pB67, mBld, acc0[3]);  acc1[3] = ffma2(pB67, mBrd, acc1[3]);
        }
        {
            const ULL pA01 = pack2(xa2.x, xa2.y), pA23 = pack2(xa2.z, xa2.w);
            const ULL pA45 = pack2(xa3.x, xa3.y), pA67 = pack2(xa3.z, xa3.w);
            const ULL pB01 = pack2(xb2.x, xb2.y), pB23 = pack2(xb2.z, xb2.w);
            const ULL pB45 = pack2(xb3.x, xb3.y), pB67 = pack2(xb3.z, xb3.w);
            acc0[4] = ffma2(pA01, mAld, acc0[4]);  acc1[4] = ffma2(pA01, mArd, acc1[4]);
            acc0[5] = ffma2(pA23, mAld, acc0[5]);  acc1[5] = ffma2(pA23, mArd, acc1[5]);
            acc0[6] = ffma2(pA45, mAld, acc0[6]);  acc1[6] = ffma2(pA45, mArd, acc1[6]);
            acc0[7] = ffma2(pA67, mAld, acc0[7]);  acc1[7] = ffma2(pA67, mArd, acc1[7]);
            acc0[4] = ffma2(pB01, mBld, acc0[4]);  acc1[4] = ffma2(pB01, mBrd, acc1[4]);
            acc0[5] = ffma2(pB23, mBld, acc0[5]);  acc1[5] = ffma2(pB23, mBrd, acc1[5]);
            acc0[6] = ffma2(pB45, mBld, acc0[6]);  acc1[6] = ffma2(pB45, mBrd, acc1[6]);
            acc0[7] = ffma2(pB67, mBld, acc0[7]);  acc1[7] = ffma2(pB67, mBrd, acc1[7]);
        }

        aix = bix; ad0 = bd0; ad1 = bd1; ad2 = bd2;
        bix = nix; bd0 = nd0; bd1 = nd1; bd2 = nd2;
    }

    // store P[n][c*64+m], applying the folded 1/cnt (coalesced 128B rows)
    float* Pn = g_P + (ULL)n * 1024;
    const ULL invd = pack2(inv, inv);
    #pragma unroll
    for (int q = 0; q < 8; ++q) {
        float a, b;
        unpack2(fmul2(acc0[q], invd), a, b);
        Pn[(2 * q)     * 64 + l] = a;
        Pn[(2 * q + 1) * 64 + l] = b;
        unpack2(fmul2(acc1[q], invd), a, b);
        Pn[(2 * q)     * 64 + l + 32] = a;
        Pn[(2 * q + 1) * 64 + l + 32] = b;
    }
}

// ---------------- Phase 2: out = P @ W3 + b3  (smem-tiled GEMM) ----------------
__global__ __launch_bounds__(256)
void gemm_kernel(const float* __restrict__ W3, const float* __restrict__ b3,
                 float* __restrict__ out, int Npts)
{
    __shared__ ULL As[32][128];   // 32 KB, dup'd P tile (transposed)
    __shared__ ULL Bs[32][32];    // 8 KB,  W3 tile (col-pairs)

    const int tid = threadIdx.x;
    const int n0  = blockIdx.x * 128;

    const int rg = tid >> 4;            // row group: rows [rg*8, rg*8+8)
    const int g  = tid & 15;            // col group: cols [g*4, g*4+4)
    const int r0 = rg * 8;

    ULL acc0[8], acc1[8];
    #pragma unroll
    for (int r = 0; r < 8; ++r) { acc0[r] = 0ull; acc1[r] = 0ull; }

    const int ra   = tid >> 1;
    const int koff = (tid & 1) * 16;
    const float* Pa = g_P + (ULL)(n0 + ra) * 1024 + koff;
    const int kb = tid >> 3;
    const int cb = (tid & 7) * 8;

    for (int kc = 0; kc < 1024; kc += 32) {
        #pragma unroll
        for (int q = 0; q < 4; ++q) {
            const float4 f = *(const float4*)(Pa + kc + q * 4);
            As[koff + q * 4    ][ra] = pack2(f.x, f.x);
            As[koff + q * 4 + 1][ra] = pack2(f.y, f.y);
            As[koff + q * 4 + 2][ra] = pack2(f.z, f.z);
            As[koff + q * 4 + 3][ra] = pack2(f.w, f.w);
        }
        {
            const float4 f0 = *(const float4*)(W3 + (kc + kb) * 64 + cb);
            const float4 f1 = *(const float4*)(W3 + (kc + kb) * 64 + cb + 4);
            *(float4*)&Bs[kb][cb >> 1]       = f0;
            *(float4*)&Bs[kb][(cb >> 1) + 2] = f1;
        }
        __syncthreads();

        #pragma unroll 16
        for (int k = 0; k < 32; ++k) {
            const ulonglong2 a01 = *(const ulonglong2*)&As[k][r0];
            const ulonglong2 a23 = *(const ulonglong2*)&As[k][r0 + 2];
            const ulonglong2 a45 = *(const ulonglong2*)&As[k][r0 + 4];
            const ulonglong2 a67 = *(const ulonglong2*)&As[k][r0 + 6];
            const ulonglong2 bb  = *(const ulonglong2*)&Bs[k][2 * g];
            acc0[0] = ffma2(a01.x, bb.x, acc0[0]);  acc1[0] = ffma2(a01.x, bb.y, acc1[0]);
            acc0[1] = ffma2(a01.y, bb.x, acc0[1]);  acc1[1] = ffma2(a01.y, bb.y, acc1[1]);
            acc0[2] = ffma2(a23.x, bb.x, acc0[2]);  acc1[2] = ffma2(a23.x, bb.y, acc1[2]);
            acc0[3] = ffma2(a23.y, bb.x, acc0[3]);  acc1[3] = ffma2(a23.y, bb.y, acc1[3]);
            acc0[4] = ffma2(a45.x, bb.x, acc0[4]);  acc1[4] = ffma2(a45.x, bb.y, acc1[4]);
            acc0[5] = ffma2(a45.y, bb.x, acc0[5]);  acc1[5] = ffma2(a45.y, bb.y, acc1[5]);
            acc0[6] = ffma2(a67.x, bb.x, acc0[6]);  acc1[6] = ffma2(a67.x, bb.y, acc1[6]);
            acc0[7] = ffma2(a67.y, bb.x, acc0[7]);  acc1[7] = ffma2(a67.y, bb.y, acc1[7]);
        }
        __syncthreads();
    }

    const ULL b3p0 = pack2(b3[4 * g],     b3[4 * g + 1]);
    const ULL b3p1 = pack2(b3[4 * g + 2], b3[4 * g + 3]);
    #pragma unroll
    for (int r = 0; r < 8; ++r) {
        const int n = n0 + r0 + r;
        if (n < Npts) {
            const ULL s0 = fadd2(acc0[r], b3p0);
            const ULL s1 = fadd2(acc1[r], b3p1);
            float4 o;
            unpack2(s0, o.x, o.y);
            unpack2(s1, o.z, o.w);
            *(float4*)(out + n * 64 + 4 * g) = o;
        }
    }
}

extern "C" void kernel_launch(void* const* d_in, const int* in_sizes, int n_in,
                              void* d_out, int out_size)
{
    const float* x_in    = (const float*)d_in[0];
    const float* pos_in  = (const float*)d_in[1];
    const float* pos_out = (const float*)d_in[2];
    const int*  in_index = (const int*)  d_in[3];
    const int* out_index = (const int*)  d_in[4];
    const float* W1 = (const float*)d_in[5];
    const float* W2 = (const float*)d_in[6];
    const float* W3 = (const float*)d_in[7];
    const float* b3 = (const float*)d_in[8];
    float* out = (float*)d_out;

    const int E    = in_sizes[3];
    const int Npts = in_sizes[0] / 16;   // x_in is [N, 16]

    starts_kernel<<<(E + 255) / 256, 256>>>(out_index, E, Npts);
    edge_kernel<<<(Npts + 3) / 4, 128>>>(x_in, pos_in, pos_out, in_index, W1, W2, Npts);
    gemm_kernel<<<(Npts + 127) / 128, 256>>>(W3, b3, out, Npts);
}